// round 13
// baseline (speedup 1.0000x reference)
#include <cuda_runtime.h>
#include <math_constants.h>

#define NB   32
#define LT   2048
#define CC   128
#define J    64          // chunks along L (one block per chunk)
#define TC   (LT / J)    // 32 rows per chunk
#define OUTW 1172        // 3*384 + 20
#define NLC  ((size_t)NB * LT * CC)          // 8,388,608
#define OUT_ELEMS ((size_t)NB * LT * OUTW)   // 76,808,192
#define NCH  (3 * NB * J)                    // 6144 chunk-blocks

// decoupled-lookback state: local aggregates (flag=1) and inclusive prefixes (flag=2)
__device__ float g_lm[NCH * CC], g_ls[NCH * CC], g_im[NCH * CC], g_is[NCH * CC];
__device__ int   g_la[NCH * CC], g_ia[NCH * CC];
__device__ int   g_flag[NCH];

__global__ void init_kernel() {
    int t = blockIdx.x * 256 + threadIdx.x;
    if (t < NCH) g_flag[t] = 0;
}

__global__ void __launch_bounds__(128) fused_kernel(const float* __restrict__ x0,
                                                    const float* __restrict__ x1,
                                                    const float* __restrict__ x2,
                                                    const float* __restrict__ dem,
                                                    const float* __restrict__ W1,
                                                    const float* __restrict__ b1,
                                                    const float* __restrict__ W2,
                                                    const float* __restrict__ b2,
                                                    float* __restrict__ out) {
    const int j = blockIdx.x, n = blockIdx.y, i = blockIdx.z;
    const int c = threadIdx.x;                    // one channel per thread
    const float* x = (i == 0) ? x0 : (i == 1) ? x1 : x2;
    const int chain = i * NB + n;
    const int b = chain * J + j;

    __shared__ float h_sh[40];
    __shared__ float d_sh[20];
    __shared__ int s_state;

    // -- demographic MLP (used by i==0 blocks; recomputed per block) ----------
    if (i == 0 && c < 40) {
        float s = b1[c];
#pragma unroll
        for (int k = 0; k < 8; ++k) s = fmaf(dem[n * 8 + k], W1[k * 40 + c], s);
        h_sh[c] = fmaxf(s, 0.f);
    }
    __syncthreads();
    if (i == 0 && c < 20) {
        float s = b2[c];
#pragma unroll
        for (int k = 0; k < 40; ++k) s = fmaf(h_sh[k], W2[k * 20 + c], s);
        d_sh[c] = fmaxf(s, 0.f);
    }

    // -- phase 1: load my chunk once, compute local aggregate -----------------
    const size_t row0 = (size_t)n * LT + (size_t)j * TC;
    const float* p = x + row0 * CC + c;

    float lm = -CUDART_INF_F, ls = 0.f;
    int la = 0;
#pragma unroll 8
    for (int t = 0; t < TC; ++t) {
        float v = p[(size_t)t * CC];              // allocates in L1 for phase 3
        ls += v;
        if (v > lm) { lm = v; la = j * TC + t; }  // strict > => earliest wins
    }

    // -- publish local aggregate (flag = 1) -----------------------------------
    g_lm[b * CC + c] = lm;
    g_la[b * CC + c] = la;
    g_ls[b * CC + c] = ls;
    __syncthreads();
    if (c == 0) {
        __threadfence();                          // cumulative: all block stores visible
        atomicExch(&g_flag[b], 1);
    }

    // -- decoupled lookback: build exclusive prefix over chunks 0..j-1 --------
    float pm = -CUDART_INF_F, ps = 0.f;
    int pa = 0;
    for (int k = j - 1; k >= 0; --k) {
        if (c == 0) {
            int s;
            do { s = *(volatile int*)&g_flag[chain * J + k]; } while (s == 0);
            s_state = s;
        }
        __syncthreads();
        const int s = s_state;
        __threadfence();                          // acquire before reading values
        const int idx = (chain * J + k) * CC + c;
        if (s == 2) {
            float m = __ldcg(&g_im[idx]);
            int   a = __ldcg(&g_ia[idx]);
            float sv = __ldcg(&g_is[idx]);
            if (m >= pm) { pm = m; pa = a; }      // earlier block wins ties
            ps += sv;
            break;                                 // inclusive prefix found
        } else {
            float m = __ldcg(&g_lm[idx]);
            int   a = __ldcg(&g_la[idx]);
            float sv = __ldcg(&g_ls[idx]);
            if (m >= pm) { pm = m; pa = a; }
            ps += sv;
        }
        __syncthreads();                          // protect s_state reuse
    }

    // -- publish inclusive prefix (flag = 2) ----------------------------------
    {
        float im = pm, is_ = ps + ls;
        int ia = pa;
        if (lm > pm) { im = lm; ia = la; }        // local later: wins only if strictly >
        g_im[b * CC + c] = im;
        g_ia[b * CC + c] = ia;
        g_is[b * CC + c] = is_;
    }
    __syncthreads();
    if (c == 0) {
        __threadfence();
        atomicExch(&g_flag[b], 2);
    }

    // -- phase 3: emit (re-read chunk from L1, run scan with exclusive prefix) -
    float* optr = out + row0 * OUTW + (size_t)i * 384 + c;
    float* iptr = out + OUT_ELEMS + (size_t)i * NLC + row0 * CC + c;
    float* aptr = iptr + 3 * NLC;
    const float inv_L = 1.0f / (float)LT;

#pragma unroll 4
    for (int t = 0; t < TC; ++t) {
        const int T = j * TC + t;
        float v = p[(size_t)t * CC];
        ps += v;
        if (v > pm) { pm = v; pa = T; }

        const bool pad = (T < LT - 1);            // window still contains left-pad zeros
        float pmax = pad ? fmaxf(pm, 0.f) : pm;
        float ind = (pad && pm < 0.f) ? (float)(T - (LT - 1)) : (float)pa;
        float pavg = ps * inv_L;
        float psum = ps * __frcp_rn((float)(T + 1));

        __stcs(optr, pmax);
        __stcs(optr + 128, pavg);
        __stcs(optr + 256, psum);
        __stcs(iptr, ind);
        __stcs(aptr, pmax);

        optr += OUTW;
        iptr += CC;
        aptr += CC;
    }

    // -- demographic broadcast cols [1152:1172) for this chunk (i==0 only) ----
    if (i == 0) {
#pragma unroll
        for (int q = c; q < TC * 20; q += CC) {
            const int t = q / 20, k = q % 20;
            __stcs(out + (row0 + t) * OUTW + 1152 + k, d_sh[k]);
        }
    }
}

extern "C" void kernel_launch(void* const* d_in, const int* in_sizes, int n_in,
                              void* d_out, int out_size) {
    const float* inp0 = (const float*)d_in[0];
    const float* inp1 = (const float*)d_in[1];
    const float* inp2 = (const float*)d_in[2];
    const float* dem  = (const float*)d_in[3];
    const float* W1   = (const float*)d_in[4];
    const float* b1   = (const float*)d_in[5];
    const float* W2   = (const float*)d_in[6];
    const float* b2   = (const float*)d_in[7];
    float* out = (float*)d_out;

    init_kernel<<<(NCH + 255) / 256, 256>>>();
    dim3 grid(J, NB, 3);                          // j fastest => predecessors launch first
    fused_kernel<<<grid, CC>>>(inp0, inp1, inp2, dem, W1, b1, W2, b2, out);
}

// round 14
// speedup vs baseline: 1.0666x; 1.0666x over previous
#include <cuda_runtime.h>
#include <math_constants.h>

#define NB   32
#define LT   2048
#define CC   128
#define J    64          // chunks along L (one block per chunk)
#define TC   (LT / J)    // 32 rows per chunk
#define OUTW 1172        // 3*384 + 20
#define NLC  ((size_t)NB * LT * CC)          // 8,388,608
#define OUT_ELEMS ((size_t)NB * LT * OUTW)   // 76,808,192
#define NCH  (3 * NB * J)                    // 6144 chunk-blocks

// decoupled-lookback state: local aggregates (flag=1) and inclusive prefixes (flag=2)
__device__ float g_lm[NCH * CC], g_ls[NCH * CC], g_im[NCH * CC], g_is[NCH * CC];
__device__ int   g_la[NCH * CC], g_ia[NCH * CC];
__device__ int   g_flag[NCH];

__global__ void init_kernel() {
    int t = blockIdx.x * 256 + threadIdx.x;
    if (t < NCH) g_flag[t] = 0;
}

__global__ void __launch_bounds__(128) fused_kernel(const float* __restrict__ x0,
                                                    const float* __restrict__ x1,
                                                    const float* __restrict__ x2,
                                                    const float* __restrict__ dem,
                                                    const float* __restrict__ W1,
                                                    const float* __restrict__ b1,
                                                    const float* __restrict__ W2,
                                                    const float* __restrict__ b2,
                                                    float* __restrict__ out) {
    const int j = blockIdx.x, n = blockIdx.y, i = blockIdx.z;
    const int c = threadIdx.x;                    // one channel per thread
    const int l = c & 31;                         // lane
    const float* x = (i == 0) ? x0 : (i == 1) ? x1 : x2;
    const int chain = i * NB + n;
    const int b = chain * J + j;

    __shared__ float h_sh[40];
    __shared__ float d_sh[20];

    // -- demographic MLP (used by i==0 blocks; recomputed per block) ----------
    if (i == 0 && c < 40) {
        float s = b1[c];
#pragma unroll
        for (int k = 0; k < 8; ++k) s = fmaf(dem[n * 8 + k], W1[k * 40 + c], s);
        h_sh[c] = fmaxf(s, 0.f);
    }
    __syncthreads();
    if (i == 0 && c < 20) {
        float s = b2[c];
#pragma unroll
        for (int k = 0; k < 40; ++k) s = fmaf(h_sh[k], W2[k * 20 + c], s);
        d_sh[c] = fmaxf(s, 0.f);
    }

    // -- phase 1: load my chunk once, compute local aggregate -----------------
    const size_t row0 = (size_t)n * LT + (size_t)j * TC;
    const float* p = x + row0 * CC + c;

    float lm = -CUDART_INF_F, ls = 0.f;
    int la = 0;
#pragma unroll 8
    for (int t = 0; t < TC; ++t) {
        float v = p[(size_t)t * CC];              // allocates in L1 for phase 3
        ls += v;
        if (v > lm) { lm = v; la = j * TC + t; }  // strict > => earliest wins
    }

    // -- publish local aggregate (flag = 1) -----------------------------------
    if (j > 0) {
        g_lm[b * CC + c] = lm;
        g_la[b * CC + c] = la;
        g_ls[b * CC + c] = ls;
        __syncthreads();
        if (c == 0) {
            __threadfence();                      // all block stores visible first
            atomicExch(&g_flag[b], 1);
        }
    }

    // -- parallel-window decoupled lookback: exclusive prefix over 0..j-1 -----
    float pm = -CUDART_INF_F, ps = 0.f;
    int pa = 0;
    if (j > 0) {
        int kHigh = j - 1;
        for (;;) {
            int kLow = kHigh - 31; if (kLow < 0) kLow = 0;
            const int nk = kHigh - kLow + 1;
            const int myk = kHigh - l;
            int f = 0;
            if (l < nk) {
                do { f = *(volatile int*)&g_flag[chain * J + myk]; } while (f == 0);
            }
            const unsigned m2 = __ballot_sync(0xFFFFFFFFu, (l < nk) && (f == 2));
            __threadfence();                      // acquire: order value reads after flags
            int stopK = -1;
            if (m2) stopK = kHigh - (__ffs(m2) - 1);   // most recent INCLUSIVE in window
            const int kEnd = (stopK >= 0) ? stopK : kLow;
#pragma unroll 4
            for (int k = kHigh; k >= kEnd; --k) {
                const int idx = (chain * J + k) * CC + c;
                float m, sv; int a;
                if (k == stopK) {
                    m = __ldcg(&g_im[idx]); a = __ldcg(&g_ia[idx]); sv = __ldcg(&g_is[idx]);
                } else {
                    m = __ldcg(&g_lm[idx]); a = __ldcg(&g_la[idx]); sv = __ldcg(&g_ls[idx]);
                }
                if (m >= pm) { pm = m; pa = a; }  // earlier chunk wins ties
                ps += sv;
            }
            if (stopK >= 0 || kLow == 0) break;   // inclusive found or chain exhausted
            kHigh = kLow - 1;
        }
    }

    // -- publish inclusive prefix (flag = 2) ----------------------------------
    {
        float im = pm, is_ = ps + ls;
        int ia = pa;
        if (lm > pm) { im = lm; ia = la; }        // local is later: wins only if strictly >
        g_im[b * CC + c] = im;
        g_ia[b * CC + c] = ia;
        g_is[b * CC + c] = is_;
    }
    __syncthreads();
    if (c == 0) {
        __threadfence();
        atomicExch(&g_flag[b], 2);
    }

    // -- phase 3: emit (re-read chunk from L1, run scan with exclusive prefix) -
    float* optr = out + row0 * OUTW + (size_t)i * 384 + c;
    float* iptr = out + OUT_ELEMS + (size_t)i * NLC + row0 * CC + c;
    float* aptr = iptr + 3 * NLC;
    const float inv_L = 1.0f / (float)LT;

#pragma unroll 4
    for (int t = 0; t < TC; ++t) {
        const int T = j * TC + t;
        float v = p[(size_t)t * CC];
        ps += v;
        if (v > pm) { pm = v; pa = T; }

        const bool pad = (T < LT - 1);            // window still contains left-pad zeros
        float pmax = pad ? fmaxf(pm, 0.f) : pm;
        float ind = (pad && pm < 0.f) ? (float)(T - (LT - 1)) : (float)pa;
        float pavg = ps * inv_L;
        float psum = ps * __frcp_rn((float)(T + 1));

        __stcs(optr, pmax);
        __stcs(optr + 128, pavg);
        __stcs(optr + 256, psum);
        __stcs(iptr, ind);
        __stcs(aptr, pmax);

        optr += OUTW;
        iptr += CC;
        aptr += CC;
    }

    // -- demographic broadcast cols [1152:1172) for this chunk (i==0 only) ----
    if (i == 0) {
#pragma unroll
        for (int q = c; q < TC * 20; q += CC) {
            const int t = q / 20, k = q % 20;
            __stcs(out + (row0 + t) * OUTW + 1152 + k, d_sh[k]);
        }
    }
}

extern "C" void kernel_launch(void* const* d_in, const int* in_sizes, int n_in,
                              void* d_out, int out_size) {
    const float* inp0 = (const float*)d_in[0];
    const float* inp1 = (const float*)d_in[1];
    const float* inp2 = (const float*)d_in[2];
    const float* dem  = (const float*)d_in[3];
    const float* W1   = (const float*)d_in[4];
    const float* b1   = (const float*)d_in[5];
    const float* W2   = (const float*)d_in[6];
    const float* b2   = (const float*)d_in[7];
    float* out = (float*)d_out;

    init_kernel<<<(NCH + 255) / 256, 256>>>();
    dim3 grid(J, NB, 3);                          // j fastest => predecessors launch first
    fused_kernel<<<grid, CC>>>(inp0, inp1, inp2, dem, W1, b1, W2, b2, out);
}